// round 13
// baseline (speedup 1.0000x reference)
#include <cuda_runtime.h>
#include <cuda_bf16.h>
#include <cstdint>

#define B_  4
#define L_  2048
#define H_  1024
#define NH_ 16
#define DK_ 64
#define ROWS_ (B_ * L_)          // 8192
#define HEADS_ (B_ * NH_)        // 64
#define NROWS_ (HEADS_ * L_)     // 131072

typedef __nv_bfloat16 bf16;

// Q pre-scale: (1/sqrt(64)) * log2(e) -> scores in log2 domain, use ex2
#define QSCALE 0.18033688011112427f

// ---- scratch (device globals; allocation-free rule) ----
__device__ bf16    g_Xhi[ROWS_ * H_];
__device__ bf16    g_Wqh[H_ * H_];
__device__ bf16    g_Wkh[H_ * H_];
__device__ bf16    g_Qb[ROWS_ * H_];    // row-major, scaled by QSCALE
__device__ bf16    g_Kb[ROWS_ * H_];
__device__ float   g_linv[NROWS_];
__device__ float   g_cs[HEADS_ * L_];
__device__ float   g_wsum[HEADS_ * H_];
__device__ float   g_ctxmean[B_ * H_];

// ---------------------------------------------------------------------------
// PTX helpers
// ---------------------------------------------------------------------------
__device__ __forceinline__ uint32_t smem_u32(const void* p) {
    return (uint32_t)__cvta_generic_to_shared(p);
}
__device__ __forceinline__ void ldsm_x4(uint32_t& r0, uint32_t& r1, uint32_t& r2,
                                        uint32_t& r3, uint32_t a) {
    asm volatile("ldmatrix.sync.aligned.m8n8.x4.shared.b16 {%0,%1,%2,%3}, [%4];"
                 : "=r"(r0), "=r"(r1), "=r"(r2), "=r"(r3) : "r"(a));
}
__device__ __forceinline__ void ldsm_x2(uint32_t& r0, uint32_t& r1, uint32_t a) {
    asm volatile("ldmatrix.sync.aligned.m8n8.x2.shared.b16 {%0,%1}, [%2];"
                 : "=r"(r0), "=r"(r1) : "r"(a));
}
__device__ __forceinline__ void mma_bf16(float* c, const uint32_t* a, const uint32_t* b) {
    asm volatile("mma.sync.aligned.m16n8k16.row.col.f32.bf16.bf16.f32 "
                 "{%0,%1,%2,%3}, {%4,%5,%6,%7}, {%8,%9}, {%0,%1,%2,%3};"
                 : "+f"(c[0]), "+f"(c[1]), "+f"(c[2]), "+f"(c[3])
                 : "r"(a[0]), "r"(a[1]), "r"(a[2]), "r"(a[3]), "r"(b[0]), "r"(b[1]));
}
__device__ __forceinline__ void cp16(uint32_t dst, const void* src) {
    asm volatile("cp.async.cg.shared.global [%0], [%1], 16;" :: "r"(dst), "l"(src));
}
#define CP_COMMIT()  asm volatile("cp.async.commit_group;" ::: "memory")
#define CP_WAIT0()   asm volatile("cp.async.wait_group 0;" ::: "memory")
#define CP_WAIT1()   asm volatile("cp.async.wait_group 1;" ::: "memory")

__device__ __forceinline__ float ex2f(float x) {
    float y;
    asm("ex2.approx.ftz.f32 %0, %1;" : "=f"(y) : "f"(x));
    return y;
}

#define PBE 72    // bf16 smem row pitch (elements)

// ---------------------------------------------------------------------------
// prep: x -> bf16; first blocks also convert weights and zero wsum
// ---------------------------------------------------------------------------
__global__ void prep_k(const float* __restrict__ x,
                       const float* __restrict__ Wq, const float* __restrict__ Wk)
{
    int i = blockIdx.x * blockDim.x + threadIdx.x;
    g_Xhi[i] = __float2bfloat16(x[i]);
    if (i < H_ * H_) {
        g_Wqh[i] = __float2bfloat16(Wq[i]);
        g_Wkh[i] = __float2bfloat16(Wk[i]);
    }
    if (i < HEADS_ * H_) g_wsum[i] = 0.f;
}

// ---------------------------------------------------------------------------
// Merged Q/K projection (bf16 mma): z=0 -> Q (alpha=QSCALE), z=1 -> K.
// Y = X @ W^T + b, bf16 out row-major. BK=64, 2-stage double buffer.
// ---------------------------------------------------------------------------
__global__ __launch_bounds__(256)
void gemm_qk(const float* __restrict__ bq, const float* __restrict__ bk)
{
    extern __shared__ __align__(16) char dsm[];
    bf16* sA[2] = { (bf16*)dsm, (bf16*)(dsm + 18432) };
    bf16* sB[2] = { (bf16*)(dsm + 36864), (bf16*)(dsm + 55296) };

    const int z = blockIdx.z;
    const bf16* Bh = z ? g_Wkh : g_Wqh;
    const float* bias = z ? bk : bq;
    const float alpha = z ? 1.0f : QSCALE;
    bf16* outB = z ? g_Kb : g_Qb;

    const int tid = threadIdx.x;
    const int warp = tid >> 5, lane = tid & 31;
    const int wm = warp >> 2, wn = warp & 3;
    const int mbase = wm * 64, nbase = wn * 32;
    const int rowB = blockIdx.y * 128;
    const int colB = blockIdx.x * 128;

    float acc[4][4][4];
#pragma unroll
    for (int i = 0; i < 4; i++)
#pragma unroll
        for (int j = 0; j < 4; j++)
#pragma unroll
            for (int p = 0; p < 4; p++) acc[i][j][p] = 0.f;

    auto loadstage = [&](int s, int t) {
        const int k0 = t * 64;
#pragma unroll
        for (int it = 0; it < 4; it++) {
            int idx = tid + it * 256;
            int row = idx >> 3, col = (idx & 7) * 8;
            cp16(smem_u32(&sA[s][row * PBE + col]),
                 g_Xhi + (size_t)(rowB + row) * H_ + k0 + col);
            cp16(smem_u32(&sB[s][row * PBE + col]),
                 Bh + (size_t)(colB + row) * H_ + k0 + col);
        }
        CP_COMMIT();
    };

    loadstage(0, 0);
    loadstage(1, 1);

    for (int t = 0; t < 16; t++) {
        if (t + 1 < 16) CP_WAIT1(); else CP_WAIT0();
        __syncthreads();
        const int s = t & 1;
        const bf16* abuf = sA[s];
        const bf16* bbuf = sB[s];

        uint32_t ah[4][4], bh[4][2];
#pragma unroll
        for (int kk = 0; kk < 64; kk += 16) {
#pragma unroll
            for (int i = 0; i < 4; i++)
                ldsm_x4(ah[i][0], ah[i][1], ah[i][2], ah[i][3],
                        smem_u32(&abuf[(mbase + i * 16 + (lane & 15)) * PBE +
                                       kk + (lane >> 4) * 8]));
#pragma unroll
            for (int j = 0; j < 4; j++)
                ldsm_x2(bh[j][0], bh[j][1],
                        smem_u32(&bbuf[(nbase + j * 8 + (lane & 7)) * PBE +
                                       kk + ((lane >> 3) & 1) * 8]));
#pragma unroll
            for (int i = 0; i < 4; i++)
#pragma unroll
                for (int j = 0; j < 4; j++)
                    mma_bf16(acc[i][j], ah[i], bh[j]);
        }
        __syncthreads();
        if (t + 2 < 16) loadstage(s, t + 2);
    }

    const int group = lane >> 2, qd = lane & 3;
#pragma unroll
    for (int i = 0; i < 4; i++) {
        const int r0 = rowB + mbase + i * 16 + group;
#pragma unroll
        for (int j = 0; j < 4; j++) {
            const int c = colB + nbase + j * 8 + qd * 2;
            const float b0 = bias[c], b1 = bias[c + 1];
#pragma unroll
            for (int half = 0; half < 2; half++) {
                const int r = r0 + half * 8;
                __nv_bfloat162 p;
                p.x = __float2bfloat16((acc[i][j][half * 2 + 0] + b0) * alpha);
                p.y = __float2bfloat16((acc[i][j][half * 2 + 1] + b1) * alpha);
                *(__nv_bfloat162*)&outB[(size_t)r * H_ + c] = p;
            }
        }
    }
}

// ---------------------------------------------------------------------------
// Pass A: rowsum, software-pipelined. Per (q-tile 128, head):
// 32 steps of (kt, j-half): MMA into buffer p while epilogue (exp2+sum)
// drains buffer p^1. Exact row sums -> g_linv.
// grid (16, 64), 256 threads, dyn smem 57344.
// ---------------------------------------------------------------------------
__global__ __launch_bounds__(256, 2)
void rowsum_k()
{
    extern __shared__ __align__(16) char dsm[];
    bf16* sQ = (bf16*)dsm;                                   // 18432
    bf16* sK[2] = { (bf16*)(dsm + 18432), (bf16*)(dsm + 36864) };
    float* rs = (float*)(dsm + 55296);                       // 2048

    const int tid = threadIdx.x;
    const int warp = tid >> 5, lane = tid & 31;
    const int wm = warp >> 2, wn = warp & 3;
    const int mbase = wm * 64, nbase = wn * 32;
    const int group = lane >> 2, qd = lane & 3;
    const int head = blockIdx.y;
    const int b = head >> 4, nh = head & 15;
    const int qB = blockIdx.x * 128;

#pragma unroll
    for (int it = 0; it < 4; it++) {
        int idx = tid + it * 256;
        int row = idx >> 3, col = (idx & 7) * 8;
        cp16(smem_u32(&sQ[row * PBE + col]),
             &g_Qb[(size_t)(b * L_ + qB + row) * H_ + nh * 64 + col]);
    }
    auto loadK = [&](int s, int kt) {
#pragma unroll
        for (int it = 0; it < 4; it++) {
            int idx = tid + it * 256;
            int row = idx >> 3, col = (idx & 7) * 8;
            cp16(smem_u32(&sK[s][row * PBE + col]),
                 &g_Kb[(size_t)(b * L_ + kt * 128 + row) * H_ + nh * 64 + col]);
        }
        CP_COMMIT();
    };
    loadK(0, 0);

    float racc[4][2];
#pragma unroll
    for (int i = 0; i < 4; i++) { racc[i][0] = 0.f; racc[i][1] = 0.f; }

    float acc[2][4][2][4];
    int step = 0;

    for (int kt = 0; kt < 16; kt++) {
        CP_WAIT0();
        __syncthreads();
        if (kt + 1 < 16) loadK((kt + 1) & 1, kt + 1);
        const bf16* kbuf = sK[kt & 1];

#pragma unroll
        for (int jh = 0; jh < 2; jh++) {
            const int p = step & 1;
            uint32_t ah[4][4], bh[2][2];
#pragma unroll
            for (int i = 0; i < 4; i++)
#pragma unroll
                for (int j2 = 0; j2 < 2; j2++)
#pragma unroll
                    for (int q4 = 0; q4 < 4; q4++) acc[p][i][j2][q4] = 0.f;

#pragma unroll
            for (int kk = 0; kk < 64; kk += 16) {
#pragma unroll
                for (int i = 0; i < 4; i++)
                    ldsm_x4(ah[i][0], ah[i][1], ah[i][2], ah[i][3],
                            smem_u32(&sQ[(mbase + i * 16 + (lane & 15)) * PBE +
                                         kk + (lane >> 4) * 8]));
#pragma unroll
                for (int j2 = 0; j2 < 2; j2++)
                    ldsm_x2(bh[j2][0], bh[j2][1],
                            smem_u32(&kbuf[(nbase + (jh * 2 + j2) * 8 + (lane & 7)) * PBE +
                                           kk + ((lane >> 3) & 1) * 8]));
#pragma unroll
                for (int i = 0; i < 4; i++)
#pragma unroll
                    for (int j2 = 0; j2 < 2; j2++)
                        mma_bf16(acc[p][i][j2], ah[i], bh[j2]);
            }

            // epilogue of PREVIOUS step's buffer (independent of the MMAs above)
            if (step > 0) {
                const int q = p ^ 1;
#pragma unroll
                for (int i = 0; i < 4; i++)
#pragma unroll
                    for (int j2 = 0; j2 < 2; j2++) {
                        racc[i][0] += ex2f(acc[q][i][j2][0]) + ex2f(acc[q][i][j2][1]);
                        racc[i][1] += ex2f(acc[q][i][j2][2]) + ex2f(acc[q][i][j2][3]);
                    }
            }
            step++;
        }
    }
    // flush last buffer
    {
        const int q = (step - 1) & 1;
#pragma unroll
        for (int i = 0; i < 4; i++)
#pragma unroll
            for (int j2 = 0; j2 < 2; j2++) {
                racc[i][0] += ex2f(acc[q][i][j2][0]) + ex2f(acc[q][i][j2][1]);
                racc[i][1] += ex2f(acc[q][i][j2][2]) + ex2f(acc[q][i][j2][3]);
            }
    }

    // row-sum reduction -> linv
#pragma unroll
    for (int i = 0; i < 4; i++)
#pragma unroll
        for (int h = 0; h < 2; h++) {
            racc[i][h] += __shfl_xor_sync(0xFFFFFFFFu, racc[i][h], 1);
            racc[i][h] += __shfl_xor_sync(0xFFFFFFFFu, racc[i][h], 2);
        }
    if (qd == 0) {
#pragma unroll
        for (int i = 0; i < 4; i++)
#pragma unroll
            for (int h = 0; h < 2; h++)
                rs[(mbase + i * 16 + group + h * 8) * 4 + wn] = racc[i][h];
    }
    __syncthreads();
    if (tid < 128)
        g_linv[head * L_ + qB + tid] =
            1.f / (rs[tid * 4] + rs[tid * 4 + 1] + rs[tid * 4 + 2] + rs[tid * 4 + 3]);
}

// ---------------------------------------------------------------------------
// Pass B: colsum via recompute, software-pipelined. Per (k-tile 128, head):
// 32 steps of (qt, j-half) with swapped operands; epilogue multiplies by the
// saved linv pair of the previous step. -> g_cs.
// grid (16, 64), 256 threads, dyn smem 65536.
// ---------------------------------------------------------------------------
__global__ __launch_bounds__(256, 2)
void colsum_k()
{
    extern __shared__ __align__(16) char dsm[];
    bf16* sK = (bf16*)dsm;                                   // 18432 (fixed)
    bf16* sQ[2] = { (bf16*)(dsm + 18432), (bf16*)(dsm + 36864) };
    float* s_li = (float*)(dsm + 55296);                     // 8192
    float* rs = (float*)(dsm + 63488);                       // 2048

    const int tid = threadIdx.x;
    const int warp = tid >> 5, lane = tid & 31;
    const int wm = warp >> 2, wn = warp & 3;
    const int mbase = wm * 64, nbase = wn * 32;
    const int group = lane >> 2, qd = lane & 3;
    const int head = blockIdx.y;
    const int b = head >> 4, nh = head & 15;
    const int kB = blockIdx.x * 128;

#pragma unroll
    for (int it = 0; it < 4; it++) {
        int idx = tid + it * 256;
        int row = idx >> 3, col = (idx & 7) * 8;
        cp16(smem_u32(&sK[row * PBE + col]),
             &g_Kb[(size_t)(b * L_ + kB + row) * H_ + nh * 64 + col]);
    }
#pragma unroll
    for (int it = 0; it < 2; it++) {
        int c4 = tid + it * 256;
        cp16(smem_u32(&s_li[c4 * 4]), &g_linv[head * L_ + c4 * 4]);
    }
    auto loadQ = [&](int s, int qt) {
#pragma unroll
        for (int it = 0; it < 4; it++) {
            int idx = tid + it * 256;
            int row = idx >> 3, col = (idx & 7) * 8;
            cp16(smem_u32(&sQ[s][row * PBE + col]),
                 &g_Qb[(size_t)(b * L_ + qt * 128 + row) * H_ + nh * 64 + col]);
        }
        CP_COMMIT();
    };
    loadQ(0, 0);

    float racc[4][2];
#pragma unroll
    for (int i = 0; i < 4; i++) { racc[i][0] = 0.f; racc[i][1] = 0.f; }

    float acc[2][4][2][4];
    float2 prevLi[2];
    int step = 0;

    for (int qt = 0; qt < 16; qt++) {
        CP_WAIT0();
        __syncthreads();
        if (qt + 1 < 16) loadQ((qt + 1) & 1, qt + 1);
        const bf16* qbuf = sQ[qt & 1];

#pragma unroll
        for (int jh = 0; jh < 2; jh++) {
            const int p = step & 1;
            uint32_t ah[4][4], bh[2][2];
            float2 curLi[2];
#pragma unroll
            for (int j2 = 0; j2 < 2; j2++)
                curLi[j2] = *(const float2*)&s_li[qt * 128 + nbase + (jh * 2 + j2) * 8 + qd * 2];
#pragma unroll
            for (int i = 0; i < 4; i++)
#pragma unroll
                for (int j2 = 0; j2 < 2; j2++)
#pragma unroll
                    for (int q4 = 0; q4 < 4; q4++) acc[p][i][j2][q4] = 0.f;

#pragma unroll
            for (int kk = 0; kk < 64; kk += 16) {
#pragma unroll
                for (int i = 0; i < 4; i++)
                    ldsm_x4(ah[i][0], ah[i][1], ah[i][2], ah[i][3],
                            smem_u32(&sK[(mbase + i * 16 + (lane & 15)) * PBE +
                                         kk + (lane >> 4) * 8]));
#pragma unroll
                for (int j2 = 0; j2 < 2; j2++)
                    ldsm_x2(bh[j2][0], bh[j2][1],
                            smem_u32(&qbuf[(nbase + (jh * 2 + j2) * 8 + (lane & 7)) * PBE +
                                           kk + ((lane >> 3) & 1) * 8]));
#pragma unroll
                for (int i = 0; i < 4; i++)
#pragma unroll
                    for (int j2 = 0; j2 < 2; j2++)
                        mma_bf16(acc[p][i][j2], ah[i], bh[j2]);
            }

            // epilogue of previous buffer with its linv pair
            if (step > 0) {
                const int q = p ^ 1;
#pragma unroll
                for (int j2 = 0; j2 < 2; j2++) {
                    const float lx = prevLi[j2].x, ly = prevLi[j2].y;
#pragma unroll
                    for (int i = 0; i < 4; i++) {
                        racc[i][0] += ex2f(acc[q][i][j2][0]) * lx + ex2f(acc[q][i][j2][1]) * ly;
                        racc[i][1] += ex2f(acc[q][i][j2][2]) * lx + ex2f(acc[q][i][j2][3]) * ly;
                    }
                }
            }
            prevLi[0] = curLi[0];
            prevLi[1] = curLi[1];
            step++;
        }
    }
    // flush last buffer
    {
        const int q = (step - 1) & 1;
#pragma unroll
        for (int j2 = 0; j2 < 2; j2++) {
            const float lx = prevLi[j2].x, ly = prevLi[j2].y;
#pragma unroll
            for (int i = 0; i < 4; i++) {
                racc[i][0] += ex2f(acc[q][i][j2][0]) * lx + ex2f(acc[q][i][j2][1]) * ly;
                racc[i][1] += ex2f(acc[q][i][j2][2]) * lx + ex2f(acc[q][i][j2][3]) * ly;
            }
        }
    }

    // per-k-row reduction -> cs
#pragma unroll
    for (int i = 0; i < 4; i++)
#pragma unroll
        for (int h = 0; h < 2; h++) {
            racc[i][h] += __shfl_xor_sync(0xFFFFFFFFu, racc[i][h], 1);
            racc[i][h] += __shfl_xor_sync(0xFFFFFFFFu, racc[i][h], 2);
        }
    if (qd == 0) {
#pragma unroll
        for (int i = 0; i < 4; i++)
#pragma unroll
            for (int h = 0; h < 2; h++)
                rs[(mbase + i * 16 + group + h * 8) * 4 + wn] = racc[i][h];
    }
    __syncthreads();
    if (tid < 128)
        g_cs[head * L_ + kB + tid] =
            rs[tid * 4] + rs[tid * 4 + 1] + rs[tid * 4 + 2] + rs[tid * 4 + 3];
}

// ---------------------------------------------------------------------------
// wsum[head][h] = (1/L) sum_k cs[head,k] * x[b*L+k, h]   (fp32 exact)
// ---------------------------------------------------------------------------
__global__ __launch_bounds__(128)
void wsum_k(const float* __restrict__ x)
{
    __shared__ float scs[16][256];
    const int tid = threadIdx.x;
    const int h  = blockIdx.x * 128 + tid;
    const int b  = blockIdx.y;
    const int k0 = blockIdx.z * 256;

#pragma unroll
    for (int it = 0; it < 32; it++) {
        int w = tid + it * 128;
        scs[w >> 8][w & 255] = g_cs[(b * NH_ + (w >> 8)) * L_ + k0 + (w & 255)];
    }
    __syncthreads();

    float acc[16];
#pragma unroll
    for (int nh = 0; nh < NH_; nh++) acc[nh] = 0.f;

    const float* xp = x + (size_t)(b * L_ + k0) * H_ + h;
#pragma unroll 4
    for (int kk = 0; kk < 256; kk++) {
        float xv = xp[(size_t)kk * H_];
#pragma unroll
        for (int nh = 0; nh < NH_; nh++) acc[nh] += scs[nh][kk] * xv;
    }
#pragma unroll
    for (int nh = 0; nh < NH_; nh++)
        atomicAdd(&g_wsum[(b * NH_ + nh) * H_ + h], acc[nh] * (1.f / (float)L_));
}

// ---------------------------------------------------------------------------
__global__ __launch_bounds__(256)
void ctx_k(const float* __restrict__ Wv, const float* __restrict__ bv)
{
    __shared__ float sw[H_];
    const int tid = threadIdx.x;
    const int warp = tid >> 5, lane = tid & 31;
    const int head = blockIdx.x;
    const int b = head >> 4, nh = head & 15;

#pragma unroll
    for (int it = 0; it < 4; it++)
        sw[tid + it * 256] = g_wsum[head * H_ + tid + it * 256];
    __syncthreads();

#pragma unroll
    for (int d = 0; d < 8; d++) {
        const int dk = warp * 8 + d;
        const float* wr = Wv + (size_t)(nh * 64 + dk) * H_;
        float acc = 0.f;
#pragma unroll 8
        for (int h = lane; h < H_; h += 32) acc += sw[h] * wr[h];
#pragma unroll
        for (int off = 16; off > 0; off >>= 1)
            acc += __shfl_xor_sync(0xFFFFFFFFu, acc, off);
        if (lane == 0)
            g_ctxmean[b * H_ + nh * 64 + dk] = acc + bv[nh * 64 + dk];
    }
}

// ---------------------------------------------------------------------------
__global__ __launch_bounds__(256)
void pooled_kernel(const float* __restrict__ Wo, const float* __restrict__ bo,
                   float* __restrict__ out)
{
    const int warp = threadIdx.x >> 5;
    const int lane = threadIdx.x & 31;
    const int idx = blockIdx.x * 8 + warp;
    const int b = idx >> 10;
    const int o = idx & 1023;

    const float* cm = g_ctxmean + b * H_;
    const float* wr = Wo + (size_t)o * H_;
    float acc = 0.f;
#pragma unroll
    for (int h = lane; h < H_; h += 32) acc += cm[h] * wr[h];
#pragma unroll
    for (int off = 16; off > 0; off >>= 1)
        acc += __shfl_xor_sync(0xFFFFFFFFu, acc, off);
    if (lane == 0) out[idx] = acc + bo[o];
}

// ---------------------------------------------------------------------------
__global__ void weights_kernel(float* __restrict__ out)
{
    int i = blockIdx.x * blockDim.x + threadIdx.x;
    if (i >= B_ * L_) return;
    int b = i >> 11;
    int k = i & (L_ - 1);
    float s = 0.f;
#pragma unroll
    for (int nh = 0; nh < NH_; nh++)
        s += g_cs[(b * NH_ + nh) * L_ + k];
    out[B_ * H_ + i] = s * (1.f / (float)(NH_ * L_));
}

// ---------------------------------------------------------------------------
extern "C" void kernel_launch(void* const* d_in, const int* in_sizes, int n_in,
                              void* d_out, int out_size)
{
    const float* x  = (const float*)d_in[0];
    const float* Wq = (const float*)d_in[1];
    const float* bq = (const float*)d_in[2];
    const float* Wk = (const float*)d_in[3];
    const float* bk = (const float*)d_in[4];
    const float* Wv = (const float*)d_in[5];
    const float* bv = (const float*)d_in[6];
    const float* Wo = (const float*)d_in[7];
    const float* bo = (const float*)d_in[8];
    float* out = (float*)d_out;

    cudaFuncSetAttribute(gemm_qk,  cudaFuncAttributeMaxDynamicSharedMemorySize, 73728);
    cudaFuncSetAttribute(rowsum_k, cudaFuncAttributeMaxDynamicSharedMemorySize, 57344);
    cudaFuncSetAttribute(colsum_k, cudaFuncAttributeMaxDynamicSharedMemorySize, 65536);

    prep_k<<<(ROWS_ * H_) / 256, 256>>>(x, Wq, Wk);

    gemm_qk<<<dim3(H_ / 128, ROWS_ / 128, 2), 256, 73728>>>(bq, bk);

    rowsum_k<<<dim3(16, HEADS_), 256, 57344>>>();
    colsum_k<<<dim3(16, HEADS_), 256, 65536>>>();

    wsum_k<<<dim3(8, B_, 8), 128>>>(x);
    ctx_k<<<HEADS_, 256>>>(Wv, bv);
    pooled_kernel<<<512, 256>>>(Wo, bo, out);
    weights_kernel<<<(B_ * L_ + 255) / 256, 256>>>(out);
}

// round 14
// speedup vs baseline: 1.0014x; 1.0014x over previous
#include <cuda_runtime.h>
#include <cuda_bf16.h>
#include <cstdint>

#define B_  4
#define L_  2048
#define H_  1024
#define NH_ 16
#define DK_ 64
#define ROWS_ (B_ * L_)          // 8192
#define HEADS_ (B_ * NH_)        // 64
#define NROWS_ (HEADS_ * L_)     // 131072

typedef __nv_bfloat16 bf16;

// Q pre-scale: (1/sqrt(64)) * log2(e) -> scores in log2 domain, use ex2
#define QSCALE 0.18033688011112427f

// ---- scratch (device globals; allocation-free rule) ----
__device__ bf16    g_Xhi[ROWS_ * H_];
__device__ bf16    g_Wqh[H_ * H_];
__device__ bf16    g_Wkh[H_ * H_];
__device__ bf16    g_Qb[ROWS_ * H_];    // row-major, scaled by QSCALE
__device__ bf16    g_Kb[ROWS_ * H_];
__device__ float   g_linv[NROWS_];
__device__ float   g_cs[HEADS_ * L_];
__device__ float   g_wsum[HEADS_ * H_];
__device__ float   g_ctxmean[B_ * H_];

// ---------------------------------------------------------------------------
// PTX helpers
// ---------------------------------------------------------------------------
__device__ __forceinline__ uint32_t smem_u32(const void* p) {
    return (uint32_t)__cvta_generic_to_shared(p);
}
__device__ __forceinline__ void ldsm_x4(uint32_t& r0, uint32_t& r1, uint32_t& r2,
                                        uint32_t& r3, uint32_t a) {
    asm volatile("ldmatrix.sync.aligned.m8n8.x4.shared.b16 {%0,%1,%2,%3}, [%4];"
                 : "=r"(r0), "=r"(r1), "=r"(r2), "=r"(r3) : "r"(a));
}
__device__ __forceinline__ void ldsm_x2(uint32_t& r0, uint32_t& r1, uint32_t a) {
    asm volatile("ldmatrix.sync.aligned.m8n8.x2.shared.b16 {%0,%1}, [%2];"
                 : "=r"(r0), "=r"(r1) : "r"(a));
}
__device__ __forceinline__ void mma_bf16(float* c, const uint32_t* a, const uint32_t* b) {
    asm volatile("mma.sync.aligned.m16n8k16.row.col.f32.bf16.bf16.f32 "
                 "{%0,%1,%2,%3}, {%4,%5,%6,%7}, {%8,%9}, {%0,%1,%2,%3};"
                 : "+f"(c[0]), "+f"(c[1]), "+f"(c[2]), "+f"(c[3])
                 : "r"(a[0]), "r"(a[1]), "r"(a[2]), "r"(a[3]), "r"(b[0]), "r"(b[1]));
}
__device__ __forceinline__ void cp16(uint32_t dst, const void* src) {
    asm volatile("cp.async.cg.shared.global [%0], [%1], 16;" :: "r"(dst), "l"(src));
}
#define CP_COMMIT()  asm volatile("cp.async.commit_group;" ::: "memory")
#define CP_WAIT0()   asm volatile("cp.async.wait_group 0;" ::: "memory")
#define CP_WAIT1()   asm volatile("cp.async.wait_group 1;" ::: "memory")

__device__ __forceinline__ float ex2f(float x) {
    float y;
    asm("ex2.approx.ftz.f32 %0, %1;" : "=f"(y) : "f"(x));
    return y;
}

#define PBE 72    // bf16 smem row pitch (elements)

// ---------------------------------------------------------------------------
// prep: x -> bf16; first blocks also convert weights and zero wsum
// ---------------------------------------------------------------------------
__global__ void prep_k(const float* __restrict__ x,
                       const float* __restrict__ Wq, const float* __restrict__ Wk)
{
    int i = blockIdx.x * blockDim.x + threadIdx.x;
    g_Xhi[i] = __float2bfloat16(x[i]);
    if (i < H_ * H_) {
        g_Wqh[i] = __float2bfloat16(Wq[i]);
        g_Wkh[i] = __float2bfloat16(Wk[i]);
    }
    if (i < HEADS_ * H_) g_wsum[i] = 0.f;
}

// ---------------------------------------------------------------------------
// Merged Q/K projection (bf16 mma): z=0 -> Q (alpha=QSCALE), z=1 -> K.
// Y = X @ W^T + b, bf16 out row-major. BK=64, 2-stage double buffer.
// ---------------------------------------------------------------------------
__global__ __launch_bounds__(256)
void gemm_qk(const float* __restrict__ bq, const float* __restrict__ bk)
{
    extern __shared__ __align__(16) char dsm[];
    bf16* sA[2] = { (bf16*)dsm, (bf16*)(dsm + 18432) };
    bf16* sB[2] = { (bf16*)(dsm + 36864), (bf16*)(dsm + 55296) };

    const int z = blockIdx.z;
    const bf16* Bh = z ? g_Wkh : g_Wqh;
    const float* bias = z ? bk : bq;
    const float alpha = z ? 1.0f : QSCALE;
    bf16* outB = z ? g_Kb : g_Qb;

    const int tid = threadIdx.x;
    const int warp = tid >> 5, lane = tid & 31;
    const int wm = warp >> 2, wn = warp & 3;
    const int mbase = wm * 64, nbase = wn * 32;
    const int rowB = blockIdx.y * 128;
    const int colB = blockIdx.x * 128;

    float acc[4][4][4];
#pragma unroll
    for (int i = 0; i < 4; i++)
#pragma unroll
        for (int j = 0; j < 4; j++)
#pragma unroll
            for (int p = 0; p < 4; p++) acc[i][j][p] = 0.f;

    auto loadstage = [&](int s, int t) {
        const int k0 = t * 64;
#pragma unroll
        for (int it = 0; it < 4; it++) {
            int idx = tid + it * 256;
            int row = idx >> 3, col = (idx & 7) * 8;
            cp16(smem_u32(&sA[s][row * PBE + col]),
                 g_Xhi + (size_t)(rowB + row) * H_ + k0 + col);
            cp16(smem_u32(&sB[s][row * PBE + col]),
                 Bh + (size_t)(colB + row) * H_ + k0 + col);
        }
        CP_COMMIT();
    };

    loadstage(0, 0);
    loadstage(1, 1);

    for (int t = 0; t < 16; t++) {
        if (t + 1 < 16) CP_WAIT1(); else CP_WAIT0();
        __syncthreads();
        const int s = t & 1;
        const bf16* abuf = sA[s];
        const bf16* bbuf = sB[s];

        uint32_t ah[4][4], bh[4][2];
#pragma unroll
        for (int kk = 0; kk < 64; kk += 16) {
#pragma unroll
            for (int i = 0; i < 4; i++)
                ldsm_x4(ah[i][0], ah[i][1], ah[i][2], ah[i][3],
                        smem_u32(&abuf[(mbase + i * 16 + (lane & 15)) * PBE +
                                       kk + (lane >> 4) * 8]));
#pragma unroll
            for (int j = 0; j < 4; j++)
                ldsm_x2(bh[j][0], bh[j][1],
                        smem_u32(&bbuf[(nbase + j * 8 + (lane & 7)) * PBE +
                                       kk + ((lane >> 3) & 1) * 8]));
#pragma unroll
            for (int i = 0; i < 4; i++)
#pragma unroll
                for (int j = 0; j < 4; j++)
                    mma_bf16(acc[i][j], ah[i], bh[j]);
        }
        __syncthreads();
        if (t + 2 < 16) loadstage(s, t + 2);
    }

    const int group = lane >> 2, qd = lane & 3;
#pragma unroll
    for (int i = 0; i < 4; i++) {
        const int r0 = rowB + mbase + i * 16 + group;
#pragma unroll
        for (int j = 0; j < 4; j++) {
            const int c = colB + nbase + j * 8 + qd * 2;
            const float b0 = bias[c], b1 = bias[c + 1];
#pragma unroll
            for (int half = 0; half < 2; half++) {
                const int r = r0 + half * 8;
                __nv_bfloat162 p;
                p.x = __float2bfloat16((acc[i][j][half * 2 + 0] + b0) * alpha);
                p.y = __float2bfloat16((acc[i][j][half * 2 + 1] + b1) * alpha);
                *(__nv_bfloat162*)&outB[(size_t)r * H_ + c] = p;
            }
        }
    }
}

// ---------------------------------------------------------------------------
// Pass A: rowsum, software-pipelined. Per (q-tile 128, head):
// 32 steps of (kt, j-half): MMA into buffer p while epilogue (exp2+sum)
// drains buffer p^1. Exact row sums -> g_linv.
// grid (16, 64), 256 threads, dyn smem 57344.
// ---------------------------------------------------------------------------
__global__ __launch_bounds__(256, 2)
void rowsum_k()
{
    extern __shared__ __align__(16) char dsm[];
    bf16* sQ = (bf16*)dsm;                                   // 18432
    bf16* sK[2] = { (bf16*)(dsm + 18432), (bf16*)(dsm + 36864) };
    float* rs = (float*)(dsm + 55296);                       // 2048

    const int tid = threadIdx.x;
    const int warp = tid >> 5, lane = tid & 31;
    const int wm = warp >> 2, wn = warp & 3;
    const int mbase = wm * 64, nbase = wn * 32;
    const int group = lane >> 2, qd = lane & 3;
    const int head = blockIdx.y;
    const int b = head >> 4, nh = head & 15;
    const int qB = blockIdx.x * 128;

#pragma unroll
    for (int it = 0; it < 4; it++) {
        int idx = tid + it * 256;
        int row = idx >> 3, col = (idx & 7) * 8;
        cp16(smem_u32(&sQ[row * PBE + col]),
             &g_Qb[(size_t)(b * L_ + qB + row) * H_ + nh * 64 + col]);
    }
    auto loadK = [&](int s, int kt) {
#pragma unroll
        for (int it = 0; it < 4; it++) {
            int idx = tid + it * 256;
            int row = idx >> 3, col = (idx & 7) * 8;
            cp16(smem_u32(&sK[s][row * PBE + col]),
                 &g_Kb[(size_t)(b * L_ + kt * 128 + row) * H_ + nh * 64 + col]);
        }
        CP_COMMIT();
    };
    loadK(0, 0);

    float racc[4][2];
#pragma unroll
    for (int i = 0; i < 4; i++) { racc[i][0] = 0.f; racc[i][1] = 0.f; }

    float acc[2][4][2][4];
    int step = 0;

    for (int kt = 0; kt < 16; kt++) {
        CP_WAIT0();
        __syncthreads();
        if (kt + 1 < 16) loadK((kt + 1) & 1, kt + 1);
        const bf16* kbuf = sK[kt & 1];

#pragma unroll
        for (int jh = 0; jh < 2; jh++) {
            const int p = step & 1;
            uint32_t ah[4][4], bh[2][2];
#pragma unroll
            for (int i = 0; i < 4; i++)
#pragma unroll
                for (int j2 = 0; j2 < 2; j2++)
#pragma unroll
                    for (int q4 = 0; q4 < 4; q4++) acc[p][i][j2][q4] = 0.f;

#pragma unroll
            for (int kk = 0; kk < 64; kk += 16) {
#pragma unroll
                for (int i = 0; i < 4; i++)
                    ldsm_x4(ah[i][0], ah[i][1], ah[i][2], ah[i][3],
                            smem_u32(&sQ[(mbase + i * 16 + (lane & 15)) * PBE +
                                         kk + (lane >> 4) * 8]));
#pragma unroll
                for (int j2 = 0; j2 < 2; j2++)
                    ldsm_x2(bh[j2][0], bh[j2][1],
                            smem_u32(&kbuf[(nbase + (jh * 2 + j2) * 8 + (lane & 7)) * PBE +
                                           kk + ((lane >> 3) & 1) * 8]));
#pragma unroll
                for (int i = 0; i < 4; i++)
#pragma unroll
                    for (int j2 = 0; j2 < 2; j2++)
                        mma_bf16(acc[p][i][j2], ah[i], bh[j2]);
            }

            // epilogue of PREVIOUS step's buffer (independent of the MMAs above)
            if (step > 0) {
                const int q = p ^ 1;
#pragma unroll
                for (int i = 0; i < 4; i++)
#pragma unroll
                    for (int j2 = 0; j2 < 2; j2++) {
                        racc[i][0] += ex2f(acc[q][i][j2][0]) + ex2f(acc[q][i][j2][1]);
                        racc[i][1] += ex2f(acc[q][i][j2][2]) + ex2f(acc[q][i][j2][3]);
                    }
            }
            step++;
        }
    }
    // flush last buffer
    {
        const int q = (step - 1) & 1;
#pragma unroll
        for (int i = 0; i < 4; i++)
#pragma unroll
            for (int j2 = 0; j2 < 2; j2++) {
                racc[i][0] += ex2f(acc[q][i][j2][0]) + ex2f(acc[q][i][j2][1]);
                racc[i][1] += ex2f(acc[q][i][j2][2]) + ex2f(acc[q][i][j2][3]);
            }
    }

    // row-sum reduction -> linv
#pragma unroll
    for (int i = 0; i < 4; i++)
#pragma unroll
        for (int h = 0; h < 2; h++) {
            racc[i][h] += __shfl_xor_sync(0xFFFFFFFFu, racc[i][h], 1);
            racc[i][h] += __shfl_xor_sync(0xFFFFFFFFu, racc[i][h], 2);
        }
    if (qd == 0) {
#pragma unroll
        for (int i = 0; i < 4; i++)
#pragma unroll
            for (int h = 0; h < 2; h++)
                rs[(mbase + i * 16 + group + h * 8) * 4 + wn] = racc[i][h];
    }
    __syncthreads();
    if (tid < 128)
        g_linv[head * L_ + qB + tid] =
            1.f / (rs[tid * 4] + rs[tid * 4 + 1] + rs[tid * 4 + 2] + rs[tid * 4 + 3]);
}

// ---------------------------------------------------------------------------
// Pass B: colsum via recompute, software-pipelined. Per (k-tile 128, head):
// 32 steps of (qt, j-half) with swapped operands; epilogue multiplies by the
// saved linv pair of the previous step. -> g_cs.
// grid (16, 64), 256 threads, dyn smem 65536.
// ---------------------------------------------------------------------------
__global__ __launch_bounds__(256, 2)
void colsum_k()
{
    extern __shared__ __align__(16) char dsm[];
    bf16* sK = (bf16*)dsm;                                   // 18432 (fixed)
    bf16* sQ[2] = { (bf16*)(dsm + 18432), (bf16*)(dsm + 36864) };
    float* s_li = (float*)(dsm + 55296);                     // 8192
    float* rs = (float*)(dsm + 63488);                       // 2048

    const int tid = threadIdx.x;
    const int warp = tid >> 5, lane = tid & 31;
    const int wm = warp >> 2, wn = warp & 3;
    const int mbase = wm * 64, nbase = wn * 32;
    const int group = lane >> 2, qd = lane & 3;
    const int head = blockIdx.y;
    const int b = head >> 4, nh = head & 15;
    const int kB = blockIdx.x * 128;

#pragma unroll
    for (int it = 0; it < 4; it++) {
        int idx = tid + it * 256;
        int row = idx >> 3, col = (idx & 7) * 8;
        cp16(smem_u32(&sK[row * PBE + col]),
             &g_Kb[(size_t)(b * L_ + kB + row) * H_ + nh * 64 + col]);
    }
#pragma unroll
    for (int it = 0; it < 2; it++) {
        int c4 = tid + it * 256;
        cp16(smem_u32(&s_li[c4 * 4]), &g_linv[head * L_ + c4 * 4]);
    }
    auto loadQ = [&](int s, int qt) {
#pragma unroll
        for (int it = 0; it < 4; it++) {
            int idx = tid + it * 256;
            int row = idx >> 3, col = (idx & 7) * 8;
            cp16(smem_u32(&sQ[s][row * PBE + col]),
                 &g_Qb[(size_t)(b * L_ + qt * 128 + row) * H_ + nh * 64 + col]);
        }
        CP_COMMIT();
    };
    loadQ(0, 0);

    float racc[4][2];
#pragma unroll
    for (int i = 0; i < 4; i++) { racc[i][0] = 0.f; racc[i][1] = 0.f; }

    float acc[2][4][2][4];
    float2 prevLi[2];
    int step = 0;

    for (int qt = 0; qt < 16; qt++) {
        CP_WAIT0();
        __syncthreads();
        if (qt + 1 < 16) loadQ((qt + 1) & 1, qt + 1);
        const bf16* qbuf = sQ[qt & 1];

#pragma unroll
        for (int jh = 0; jh < 2; jh++) {
            const int p = step & 1;
            uint32_t ah[4][4], bh[2][2];
            float2 curLi[2];
#pragma unroll
            for (int j2 = 0; j2 < 2; j2++)
                curLi[j2] = *(const float2*)&s_li[qt * 128 + nbase + (jh * 2 + j2) * 8 + qd * 2];
#pragma unroll
            for (int i = 0; i < 4; i++)
#pragma unroll
                for (int j2 = 0; j2 < 2; j2++)
#pragma unroll
                    for (int q4 = 0; q4 < 4; q4++) acc[p][i][j2][q4] = 0.f;

#pragma unroll
            for (int kk = 0; kk < 64; kk += 16) {
#pragma unroll
                for (int i = 0; i < 4; i++)
                    ldsm_x4(ah[i][0], ah[i][1], ah[i][2], ah[i][3],
                            smem_u32(&sK[(mbase + i * 16 + (lane & 15)) * PBE +
                                         kk + (lane >> 4) * 8]));
#pragma unroll
                for (int j2 = 0; j2 < 2; j2++)
                    ldsm_x2(bh[j2][0], bh[j2][1],
                            smem_u32(&qbuf[(nbase + (jh * 2 + j2) * 8 + (lane & 7)) * PBE +
                                           kk + ((lane >> 3) & 1) * 8]));
#pragma unroll
                for (int i = 0; i < 4; i++)
#pragma unroll
                    for (int j2 = 0; j2 < 2; j2++)
                        mma_bf16(acc[p][i][j2], ah[i], bh[j2]);
            }

            // epilogue of previous buffer with its linv pair
            if (step > 0) {
                const int q = p ^ 1;
#pragma unroll
                for (int j2 = 0; j2 < 2; j2++) {
                    const float lx = prevLi[j2].x, ly = prevLi[j2].y;
#pragma unroll
                    for (int i = 0; i < 4; i++) {
                        racc[i][0] += ex2f(acc[q][i][j2][0]) * lx + ex2f(acc[q][i][j2][1]) * ly;
                        racc[i][1] += ex2f(acc[q][i][j2][2]) * lx + ex2f(acc[q][i][j2][3]) * ly;
                    }
                }
            }
            prevLi[0] = curLi[0];
            prevLi[1] = curLi[1];
            step++;
        }
    }
    // flush last buffer
    {
        const int q = (step - 1) & 1;
#pragma unroll
        for (int j2 = 0; j2 < 2; j2++) {
            const float lx = prevLi[j2].x, ly = prevLi[j2].y;
#pragma unroll
            for (int i = 0; i < 4; i++) {
                racc[i][0] += ex2f(acc[q][i][j2][0]) * lx + ex2f(acc[q][i][j2][1]) * ly;
                racc[i][1] += ex2f(acc[q][i][j2][2]) * lx + ex2f(acc[q][i][j2][3]) * ly;
            }
        }
    }

    // per-k-row reduction -> cs
#pragma unroll
    for (int i = 0; i < 4; i++)
#pragma unroll
        for (int h = 0; h < 2; h++) {
            racc[i][h] += __shfl_xor_sync(0xFFFFFFFFu, racc[i][h], 1);
            racc[i][h] += __shfl_xor_sync(0xFFFFFFFFu, racc[i][h], 2);
        }
    if (qd == 0) {
#pragma unroll
        for (int i = 0; i < 4; i++)
#pragma unroll
            for (int h = 0; h < 2; h++)
                rs[(mbase + i * 16 + group + h * 8) * 4 + wn] = racc[i][h];
    }
    __syncthreads();
    if (tid < 128)
        g_cs[head * L_ + kB + tid] =
            rs[tid * 4] + rs[tid * 4 + 1] + rs[tid * 4 + 2] + rs[tid * 4 + 3];
}

// ---------------------------------------------------------------------------
// wsum[head][h] = (1/L) sum_k cs[head,k] * x[b*L+k, h]   (fp32 exact)
// ---------------------------------------------------------------------------
__global__ __launch_bounds__(128)
void wsum_k(const float* __restrict__ x)
{
    __shared__ float scs[16][256];
    const int tid = threadIdx.x;
    const int h  = blockIdx.x * 128 + tid;
    const int b  = blockIdx.y;
    const int k0 = blockIdx.z * 256;

#pragma unroll
    for (int it = 0; it < 32; it++) {
        int w = tid + it * 128;
        scs[w >> 8][w & 255] = g_cs[(b * NH_ + (w >> 8)) * L_ + k0 + (w & 255)];
    }
    __syncthreads();

    float acc[16];
#pragma unroll
    for (int nh = 0; nh < NH_; nh++) acc[nh] = 0.f;

    const float* xp = x + (size_t)(b * L_ + k0) * H_ + h;
#pragma unroll 4
    for (int kk = 0; kk < 256; kk++) {
        float xv = xp[(size_t)kk * H_];
#pragma unroll
        for (int nh = 0; nh < NH_; nh++) acc[nh] += scs[nh][kk] * xv;
    }
#pragma unroll
    for (int nh = 0; nh < NH_; nh++)
        atomicAdd(&g_wsum[(b * NH_ + nh) * H_ + h], acc[nh] * (1.f / (float)L_));
}

// ---------------------------------------------------------------------------
__global__ __launch_bounds__(256)
void ctx_k(const float* __restrict__ Wv, const float* __restrict__ bv)
{
    __shared__ float sw[H_];
    const int tid = threadIdx.x;
    const int warp = tid >> 5, lane = tid & 31;
    const int head = blockIdx.x;
    const int b = head >> 4, nh = head & 15;

#pragma unroll
    for (int it = 0; it < 4; it++)
        sw[tid + it * 256] = g_wsum[head * H_ + tid + it * 256];
    __syncthreads();

#pragma unroll
    for (int d = 0; d < 8; d++) {
        const int dk = warp * 8 + d;
        const float* wr = Wv + (size_t)(nh * 64 + dk) * H_;
        float acc = 0.f;
#pragma unroll 8
        for (int h = lane; h < H_; h += 32) acc += sw[h] * wr[h];
#pragma unroll
        for (int off = 16; off > 0; off >>= 1)
            acc += __shfl_xor_sync(0xFFFFFFFFu, acc, off);
        if (lane == 0)
            g_ctxmean[b * H_ + nh * 64 + dk] = acc + bv[nh * 64 + dk];
    }
}

// ---------------------------------------------------------------------------
__global__ __launch_bounds__(256)
void pooled_kernel(const float* __restrict__ Wo, const float* __restrict__ bo,
                   float* __restrict__ out)
{
    const int warp = threadIdx.x >> 5;
    const int lane = threadIdx.x & 31;
    const int idx = blockIdx.x * 8 + warp;
    const int b = idx >> 10;
    const int o = idx & 1023;

    const float* cm = g_ctxmean + b * H_;
    const float* wr = Wo + (size_t)o * H_;
    float acc = 0.f;
#pragma unroll
    for (int h = lane; h < H_; h += 32) acc += cm[h] * wr[h];
#pragma unroll
    for (int off = 16; off > 0; off >>= 1)
        acc += __shfl_xor_sync(0xFFFFFFFFu, acc, off);
    if (lane == 0) out[idx] = acc + bo[o];
}

// ---------------------------------------------------------------------------
__global__ void weights_kernel(float* __restrict__ out)
{
    int i = blockIdx.x * blockDim.x + threadIdx.x;
    if (i >= B_ * L_) return;
    int b = i >> 11;
    int k = i & (L_ - 1);
    float s = 0.f;
#pragma unroll
    for (int nh = 0; nh < NH_; nh++)
        s += g_cs[(b * NH_ + nh) * L_ + k];
    out[B_ * H_ + i] = s * (1.f / (float)(NH_ * L_));
}

// ---------------------------------------------------------------------------
extern "C" void kernel_launch(void* const* d_in, const int* in_sizes, int n_in,
                              void* d_out, int out_size)
{
    const float* x  = (const float*)d_in[0];
    const float* Wq = (const float*)d_in[1];
    const float* bq = (const float*)d_in[2];
    const float* Wk = (const float*)d_in[3];
    const float* bk = (const float*)d_in[4];
    const float* Wv = (const float*)d_in[5];
    const float* bv = (const float*)d_in[6];
    const float* Wo = (const float*)d_in[7];
    const float* bo = (const float*)d_in[8];
    float* out = (float*)d_out;

    cudaFuncSetAttribute(gemm_qk,  cudaFuncAttributeMaxDynamicSharedMemorySize, 73728);
    cudaFuncSetAttribute(rowsum_k, cudaFuncAttributeMaxDynamicSharedMemorySize, 57344);
    cudaFuncSetAttribute(colsum_k, cudaFuncAttributeMaxDynamicSharedMemorySize, 65536);

    prep_k<<<(ROWS_ * H_) / 256, 256>>>(x, Wq, Wk);

    gemm_qk<<<dim3(H_ / 128, ROWS_ / 128, 2), 256, 73728>>>(bq, bk);

    rowsum_k<<<dim3(16, HEADS_), 256, 57344>>>();
    colsum_k<<<dim3(16, HEADS_), 256, 65536>>>();

    wsum_k<<<dim3(8, B_, 8), 128>>>(x);
    ctx_k<<<HEADS_, 256>>>(Wv, bv);
    pooled_kernel<<<512, 256>>>(Wo, bo, out);
    weights_kernel<<<(B_ * L_ + 255) / 256, 256>>>(out);
}

// round 15
// speedup vs baseline: 1.0526x; 1.0511x over previous
#include <cuda_runtime.h>
#include <cuda_bf16.h>
#include <cstdint>

#define B_  4
#define L_  2048
#define H_  1024
#define NH_ 16
#define DK_ 64
#define ROWS_ (B_ * L_)          // 8192
#define HEADS_ (B_ * NH_)        // 64
#define NROWS_ (HEADS_ * L_)     // 131072

typedef __nv_bfloat16 bf16;

// Q pre-scale: (1/sqrt(64)) * log2(e) -> scores in log2 domain, use ex2
#define QSCALE 0.18033688011112427f

// ---- scratch (device globals; allocation-free rule) ----
__device__ bf16    g_Xhi[ROWS_ * H_];
__device__ bf16    g_Wqh[H_ * H_];
__device__ bf16    g_Wkh[H_ * H_];
__device__ bf16    g_Qb[ROWS_ * H_];    // row-major, scaled by QSCALE
__device__ bf16    g_Kb[ROWS_ * H_];
__device__ float   g_linv[NROWS_];
__device__ float   g_cs[HEADS_ * L_];
__device__ float   g_wsum[HEADS_ * H_];
__device__ float   g_ctxmean[B_ * H_];

// ---------------------------------------------------------------------------
// PTX helpers
// ---------------------------------------------------------------------------
__device__ __forceinline__ uint32_t smem_u32(const void* p) {
    return (uint32_t)__cvta_generic_to_shared(p);
}
__device__ __forceinline__ void ldsm_x4(uint32_t& r0, uint32_t& r1, uint32_t& r2,
                                        uint32_t& r3, uint32_t a) {
    asm volatile("ldmatrix.sync.aligned.m8n8.x4.shared.b16 {%0,%1,%2,%3}, [%4];"
                 : "=r"(r0), "=r"(r1), "=r"(r2), "=r"(r3) : "r"(a));
}
__device__ __forceinline__ void ldsm_x2(uint32_t& r0, uint32_t& r1, uint32_t a) {
    asm volatile("ldmatrix.sync.aligned.m8n8.x2.shared.b16 {%0,%1}, [%2];"
                 : "=r"(r0), "=r"(r1) : "r"(a));
}
__device__ __forceinline__ void mma_bf16(float* c, const uint32_t* a, const uint32_t* b) {
    asm volatile("mma.sync.aligned.m16n8k16.row.col.f32.bf16.bf16.f32 "
                 "{%0,%1,%2,%3}, {%4,%5,%6,%7}, {%8,%9}, {%0,%1,%2,%3};"
                 : "+f"(c[0]), "+f"(c[1]), "+f"(c[2]), "+f"(c[3])
                 : "r"(a[0]), "r"(a[1]), "r"(a[2]), "r"(a[3]), "r"(b[0]), "r"(b[1]));
}
__device__ __forceinline__ void cp16(uint32_t dst, const void* src) {
    asm volatile("cp.async.cg.shared.global [%0], [%1], 16;" :: "r"(dst), "l"(src));
}
#define CP_COMMIT()  asm volatile("cp.async.commit_group;" ::: "memory")
#define CP_WAIT0()   asm volatile("cp.async.wait_group 0;" ::: "memory")
#define CP_WAIT1()   asm volatile("cp.async.wait_group 1;" ::: "memory")

__device__ __forceinline__ float ex2f(float x) {
    float y;
    asm("ex2.approx.ftz.f32 %0, %1;" : "=f"(y) : "f"(x));
    return y;
}

#define PBE 72    // bf16 smem row pitch (elements)

// ---------------------------------------------------------------------------
// prep: x -> bf16; first blocks also convert weights and zero wsum
// ---------------------------------------------------------------------------
__global__ void prep_k(const float* __restrict__ x,
                       const float* __restrict__ Wq, const float* __restrict__ Wk)
{
    int i = blockIdx.x * blockDim.x + threadIdx.x;
    g_Xhi[i] = __float2bfloat16(x[i]);
    if (i < H_ * H_) {
        g_Wqh[i] = __float2bfloat16(Wq[i]);
        g_Wkh[i] = __float2bfloat16(Wk[i]);
    }
    if (i < HEADS_ * H_) g_wsum[i] = 0.f;
}

// ---------------------------------------------------------------------------
// Merged Q/K projection (bf16 mma): z=0 -> Q (alpha=QSCALE), z=1 -> K.
// Y = X @ W^T + b, bf16 out row-major. BK=64, 2-stage double buffer.
// ---------------------------------------------------------------------------
__global__ __launch_bounds__(256)
void gemm_qk(const float* __restrict__ bq, const float* __restrict__ bk)
{
    extern __shared__ __align__(16) char dsm[];
    bf16* sA[2] = { (bf16*)dsm, (bf16*)(dsm + 18432) };
    bf16* sB[2] = { (bf16*)(dsm + 36864), (bf16*)(dsm + 55296) };

    const int z = blockIdx.z;
    const bf16* Bh = z ? g_Wkh : g_Wqh;
    const float* bias = z ? bk : bq;
    const float alpha = z ? 1.0f : QSCALE;
    bf16* outB = z ? g_Kb : g_Qb;

    const int tid = threadIdx.x;
    const int warp = tid >> 5, lane = tid & 31;
    const int wm = warp >> 2, wn = warp & 3;
    const int mbase = wm * 64, nbase = wn * 32;
    const int rowB = blockIdx.y * 128;
    const int colB = blockIdx.x * 128;

    float acc[4][4][4];
#pragma unroll
    for (int i = 0; i < 4; i++)
#pragma unroll
        for (int j = 0; j < 4; j++)
#pragma unroll
            for (int p = 0; p < 4; p++) acc[i][j][p] = 0.f;

    auto loadstage = [&](int s, int t) {
        const int k0 = t * 64;
#pragma unroll
        for (int it = 0; it < 4; it++) {
            int idx = tid + it * 256;
            int row = idx >> 3, col = (idx & 7) * 8;
            cp16(smem_u32(&sA[s][row * PBE + col]),
                 g_Xhi + (size_t)(rowB + row) * H_ + k0 + col);
            cp16(smem_u32(&sB[s][row * PBE + col]),
                 Bh + (size_t)(colB + row) * H_ + k0 + col);
        }
        CP_COMMIT();
    };

    loadstage(0, 0);
    loadstage(1, 1);

    for (int t = 0; t < 16; t++) {
        if (t + 1 < 16) CP_WAIT1(); else CP_WAIT0();
        __syncthreads();
        const int s = t & 1;
        const bf16* abuf = sA[s];
        const bf16* bbuf = sB[s];

        uint32_t ah[4][4], bh[4][2];
#pragma unroll
        for (int kk = 0; kk < 64; kk += 16) {
#pragma unroll
            for (int i = 0; i < 4; i++)
                ldsm_x4(ah[i][0], ah[i][1], ah[i][2], ah[i][3],
                        smem_u32(&abuf[(mbase + i * 16 + (lane & 15)) * PBE +
                                       kk + (lane >> 4) * 8]));
#pragma unroll
            for (int j = 0; j < 4; j++)
                ldsm_x2(bh[j][0], bh[j][1],
                        smem_u32(&bbuf[(nbase + j * 8 + (lane & 7)) * PBE +
                                       kk + ((lane >> 3) & 1) * 8]));
#pragma unroll
            for (int i = 0; i < 4; i++)
#pragma unroll
                for (int j = 0; j < 4; j++)
                    mma_bf16(acc[i][j], ah[i], bh[j]);
        }
        __syncthreads();
        if (t + 2 < 16) loadstage(s, t + 2);
    }

    const int group = lane >> 2, qd = lane & 3;
#pragma unroll
    for (int i = 0; i < 4; i++) {
        const int r0 = rowB + mbase + i * 16 + group;
#pragma unroll
        for (int j = 0; j < 4; j++) {
            const int c = colB + nbase + j * 8 + qd * 2;
            const float b0 = bias[c], b1 = bias[c + 1];
#pragma unroll
            for (int half = 0; half < 2; half++) {
                const int r = r0 + half * 8;
                __nv_bfloat162 p;
                p.x = __float2bfloat16((acc[i][j][half * 2 + 0] + b0) * alpha);
                p.y = __float2bfloat16((acc[i][j][half * 2 + 1] + b1) * alpha);
                *(__nv_bfloat162*)&outB[(size_t)r * H_ + c] = p;
            }
        }
    }
}

// ---------------------------------------------------------------------------
// Pass A: rowsum. Per (q-tile 128, head): Q fragments HOISTED to registers
// once (64 regs); loop 16 K-tiles in two j-halves (acc 32 regs) with
// immediate epilogue. Exact row sums -> g_linv.
// grid (16, 64), 256 threads, dyn smem 57344.
// ---------------------------------------------------------------------------
__global__ __launch_bounds__(256, 2)
void rowsum_k()
{
    extern __shared__ __align__(16) char dsm[];
    bf16* sQ = (bf16*)dsm;                                   // 18432
    bf16* sK[2] = { (bf16*)(dsm + 18432), (bf16*)(dsm + 36864) };
    float* rs = (float*)(dsm + 55296);                       // 2048

    const int tid = threadIdx.x;
    const int warp = tid >> 5, lane = tid & 31;
    const int wm = warp >> 2, wn = warp & 3;
    const int mbase = wm * 64, nbase = wn * 32;
    const int group = lane >> 2, qd = lane & 3;
    const int head = blockIdx.y;
    const int b = head >> 4, nh = head & 15;
    const int qB = blockIdx.x * 128;

#pragma unroll
    for (int it = 0; it < 4; it++) {
        int idx = tid + it * 256;
        int row = idx >> 3, col = (idx & 7) * 8;
        cp16(smem_u32(&sQ[row * PBE + col]),
             &g_Qb[(size_t)(b * L_ + qB + row) * H_ + nh * 64 + col]);
    }
    auto loadK = [&](int s, int kt) {
#pragma unroll
        for (int it = 0; it < 4; it++) {
            int idx = tid + it * 256;
            int row = idx >> 3, col = (idx & 7) * 8;
            cp16(smem_u32(&sK[s][row * PBE + col]),
                 &g_Kb[(size_t)(b * L_ + kt * 128 + row) * H_ + nh * 64 + col]);
        }
        CP_COMMIT();
    };
    loadK(0, 0);   // commits Q loads too

    float racc[4][2];
#pragma unroll
    for (int i = 0; i < 4; i++) { racc[i][0] = 0.f; racc[i][1] = 0.f; }

    uint32_t aq[4][4][4];   // hoisted Q fragments: [m-subtile][k-step][frag]

    for (int kt = 0; kt < 16; kt++) {
        CP_WAIT0();
        __syncthreads();
        if (kt == 0) {
            // one-time Q fragment load (sQ is now resident)
#pragma unroll
            for (int i = 0; i < 4; i++)
#pragma unroll
                for (int kk = 0; kk < 4; kk++)
                    ldsm_x4(aq[i][kk][0], aq[i][kk][1], aq[i][kk][2], aq[i][kk][3],
                            smem_u32(&sQ[(mbase + i * 16 + (lane & 15)) * PBE +
                                         kk * 16 + (lane >> 4) * 8]));
        }
        if (kt + 1 < 16) loadK((kt + 1) & 1, kt + 1);
        const bf16* kbuf = sK[kt & 1];

#pragma unroll
        for (int jh = 0; jh < 2; jh++) {
            float acc[4][2][4];
            uint32_t bh[4][2][2];
#pragma unroll
            for (int i = 0; i < 4; i++)
#pragma unroll
                for (int j2 = 0; j2 < 2; j2++)
#pragma unroll
                    for (int p = 0; p < 4; p++) acc[i][j2][p] = 0.f;
#pragma unroll
            for (int kk = 0; kk < 4; kk++)
#pragma unroll
                for (int j2 = 0; j2 < 2; j2++)
                    ldsm_x2(bh[kk][j2][0], bh[kk][j2][1],
                            smem_u32(&kbuf[(nbase + (jh * 2 + j2) * 8 + (lane & 7)) * PBE +
                                           kk * 16 + ((lane >> 3) & 1) * 8]));
#pragma unroll
            for (int kk = 0; kk < 4; kk++)
#pragma unroll
                for (int i = 0; i < 4; i++)
#pragma unroll
                    for (int j2 = 0; j2 < 2; j2++)
                        mma_bf16(acc[i][j2], aq[i][kk], bh[kk][j2]);

            // epilogue: exp2, rowsum
#pragma unroll
            for (int i = 0; i < 4; i++)
#pragma unroll
                for (int j2 = 0; j2 < 2; j2++) {
                    racc[i][0] += ex2f(acc[i][j2][0]) + ex2f(acc[i][j2][1]);
                    racc[i][1] += ex2f(acc[i][j2][2]) + ex2f(acc[i][j2][3]);
                }
        }
    }

    // row-sum reduction -> linv
#pragma unroll
    for (int i = 0; i < 4; i++)
#pragma unroll
        for (int h = 0; h < 2; h++) {
            racc[i][h] += __shfl_xor_sync(0xFFFFFFFFu, racc[i][h], 1);
            racc[i][h] += __shfl_xor_sync(0xFFFFFFFFu, racc[i][h], 2);
        }
    if (qd == 0) {
#pragma unroll
        for (int i = 0; i < 4; i++)
#pragma unroll
            for (int h = 0; h < 2; h++)
                rs[(mbase + i * 16 + group + h * 8) * 4 + wn] = racc[i][h];
    }
    __syncthreads();
    if (tid < 128)
        g_linv[head * L_ + qB + tid] =
            1.f / (rs[tid * 4] + rs[tid * 4 + 1] + rs[tid * 4 + 2] + rs[tid * 4 + 3]);
}

// ---------------------------------------------------------------------------
// Pass B: colsum via recompute. Per (k-tile 128, head): K fragments HOISTED;
// loop 16 Q-tiles in two j-halves; epilogue multiplies by linv. -> g_cs.
// grid (16, 64), 256 threads, dyn smem 65536.
// ---------------------------------------------------------------------------
__global__ __launch_bounds__(256, 2)
void colsum_k()
{
    extern __shared__ __align__(16) char dsm[];
    bf16* sK = (bf16*)dsm;                                   // 18432 (fixed)
    bf16* sQ[2] = { (bf16*)(dsm + 18432), (bf16*)(dsm + 36864) };
    float* s_li = (float*)(dsm + 55296);                     // 8192
    float* rs = (float*)(dsm + 63488);                       // 2048

    const int tid = threadIdx.x;
    const int warp = tid >> 5, lane = tid & 31;
    const int wm = warp >> 2, wn = warp & 3;
    const int mbase = wm * 64, nbase = wn * 32;
    const int group = lane >> 2, qd = lane & 3;
    const int head = blockIdx.y;
    const int b = head >> 4, nh = head & 15;
    const int kB = blockIdx.x * 128;

#pragma unroll
    for (int it = 0; it < 4; it++) {
        int idx = tid + it * 256;
        int row = idx >> 3, col = (idx & 7) * 8;
        cp16(smem_u32(&sK[row * PBE + col]),
             &g_Kb[(size_t)(b * L_ + kB + row) * H_ + nh * 64 + col]);
    }
#pragma unroll
    for (int it = 0; it < 2; it++) {
        int c4 = tid + it * 256;
        cp16(smem_u32(&s_li[c4 * 4]), &g_linv[head * L_ + c4 * 4]);
    }
    auto loadQ = [&](int s, int qt) {
#pragma unroll
        for (int it = 0; it < 4; it++) {
            int idx = tid + it * 256;
            int row = idx >> 3, col = (idx & 7) * 8;
            cp16(smem_u32(&sQ[s][row * PBE + col]),
                 &g_Qb[(size_t)(b * L_ + qt * 128 + row) * H_ + nh * 64 + col]);
        }
        CP_COMMIT();
    };
    loadQ(0, 0);   // commits K + linv loads too

    float racc[4][2];
#pragma unroll
    for (int i = 0; i < 4; i++) { racc[i][0] = 0.f; racc[i][1] = 0.f; }

    uint32_t ak[4][4][4];   // hoisted K fragments

    for (int qt = 0; qt < 16; qt++) {
        CP_WAIT0();
        __syncthreads();
        if (qt == 0) {
#pragma unroll
            for (int i = 0; i < 4; i++)
#pragma unroll
                for (int kk = 0; kk < 4; kk++)
                    ldsm_x4(ak[i][kk][0], ak[i][kk][1], ak[i][kk][2], ak[i][kk][3],
                            smem_u32(&sK[(mbase + i * 16 + (lane & 15)) * PBE +
                                         kk * 16 + (lane >> 4) * 8]));
        }
        if (qt + 1 < 16) loadQ((qt + 1) & 1, qt + 1);
        const bf16* qbuf = sQ[qt & 1];

#pragma unroll
        for (int jh = 0; jh < 2; jh++) {
            float acc[4][2][4];
            uint32_t bh[4][2][2];
            float2 li[2];
#pragma unroll
            for (int j2 = 0; j2 < 2; j2++)
                li[j2] = *(const float2*)&s_li[qt * 128 + nbase + (jh * 2 + j2) * 8 + qd * 2];
#pragma unroll
            for (int i = 0; i < 4; i++)
#pragma unroll
                for (int j2 = 0; j2 < 2; j2++)
#pragma unroll
                    for (int p = 0; p < 4; p++) acc[i][j2][p] = 0.f;
#pragma unroll
            for (int kk = 0; kk < 4; kk++)
#pragma unroll
                for (int j2 = 0; j2 < 2; j2++)
                    ldsm_x2(bh[kk][j2][0], bh[kk][j2][1],
                            smem_u32(&qbuf[(nbase + (jh * 2 + j2) * 8 + (lane & 7)) * PBE +
                                           kk * 16 + ((lane >> 3) & 1) * 8]));
#pragma unroll
            for (int kk = 0; kk < 4; kk++)
#pragma unroll
                for (int i = 0; i < 4; i++)
#pragma unroll
                    for (int j2 = 0; j2 < 2; j2++)
                        mma_bf16(acc[i][j2], ak[i][kk], bh[kk][j2]);

            // epilogue: exp2 * linv[q], accumulate per k-row
#pragma unroll
            for (int j2 = 0; j2 < 2; j2++) {
                const float lx = li[j2].x, ly = li[j2].y;
#pragma unroll
                for (int i = 0; i < 4; i++) {
                    racc[i][0] += ex2f(acc[i][j2][0]) * lx + ex2f(acc[i][j2][1]) * ly;
                    racc[i][1] += ex2f(acc[i][j2][2]) * lx + ex2f(acc[i][j2][3]) * ly;
                }
            }
        }
    }

    // per-k-row reduction -> cs
#pragma unroll
    for (int i = 0; i < 4; i++)
#pragma unroll
        for (int h = 0; h < 2; h++) {
            racc[i][h] += __shfl_xor_sync(0xFFFFFFFFu, racc[i][h], 1);
            racc[i][h] += __shfl_xor_sync(0xFFFFFFFFu, racc[i][h], 2);
        }
    if (qd == 0) {
#pragma unroll
        for (int i = 0; i < 4; i++)
#pragma unroll
            for (int h = 0; h < 2; h++)
                rs[(mbase + i * 16 + group + h * 8) * 4 + wn] = racc[i][h];
    }
    __syncthreads();
    if (tid < 128)
        g_cs[head * L_ + kB + tid] =
            rs[tid * 4] + rs[tid * 4 + 1] + rs[tid * 4 + 2] + rs[tid * 4 + 3];
}

// ---------------------------------------------------------------------------
// wsum[head][h] = (1/L) sum_k cs[head,k] * x[b*L+k, h]   (fp32 exact)
// ---------------------------------------------------------------------------
__global__ __launch_bounds__(128)
void wsum_k(const float* __restrict__ x)
{
    __shared__ float scs[16][256];
    const int tid = threadIdx.x;
    const int h  = blockIdx.x * 128 + tid;
    const int b  = blockIdx.y;
    const int k0 = blockIdx.z * 256;

#pragma unroll
    for (int it = 0; it < 32; it++) {
        int w = tid + it * 128;
        scs[w >> 8][w & 255] = g_cs[(b * NH_ + (w >> 8)) * L_ + k0 + (w & 255)];
    }
    __syncthreads();

    float acc[16];
#pragma unroll
    for (int nh = 0; nh < NH_; nh++) acc[nh] = 0.f;

    const float* xp = x + (size_t)(b * L_ + k0) * H_ + h;
#pragma unroll 4
    for (int kk = 0; kk < 256; kk++) {
        float xv = xp[(size_t)kk * H_];
#pragma unroll
        for (int nh = 0; nh < NH_; nh++) acc[nh] += scs[nh][kk] * xv;
    }
#pragma unroll
    for (int nh = 0; nh < NH_; nh++)
        atomicAdd(&g_wsum[(b * NH_ + nh) * H_ + h], acc[nh] * (1.f / (float)L_));
}

// ---------------------------------------------------------------------------
__global__ __launch_bounds__(256)
void ctx_k(const float* __restrict__ Wv, const float* __restrict__ bv)
{
    __shared__ float sw[H_];
    const int tid = threadIdx.x;
    const int warp = tid >> 5, lane = tid & 31;
    const int head = blockIdx.x;
    const int b = head >> 4, nh = head & 15;

#pragma unroll
    for (int it = 0; it < 4; it++)
        sw[tid + it * 256] = g_wsum[head * H_ + tid + it * 256];
    __syncthreads();

#pragma unroll
    for (int d = 0; d < 8; d++) {
        const int dk = warp * 8 + d;
        const float* wr = Wv + (size_t)(nh * 64 + dk) * H_;
        float acc = 0.f;
#pragma unroll 8
        for (int h = lane; h < H_; h += 32) acc += sw[h] * wr[h];
#pragma unroll
        for (int off = 16; off > 0; off >>= 1)
            acc += __shfl_xor_sync(0xFFFFFFFFu, acc, off);
        if (lane == 0)
            g_ctxmean[b * H_ + nh * 64 + dk] = acc + bv[nh * 64 + dk];
    }
}

// ---------------------------------------------------------------------------
__global__ __launch_bounds__(256)
void pooled_kernel(const float* __restrict__ Wo, const float* __restrict__ bo,
                   float* __restrict__ out)
{
    const int warp = threadIdx.x >> 5;
    const int lane = threadIdx.x & 31;
    const int idx = blockIdx.x * 8 + warp;
    const int b = idx >> 10;
    const int o = idx & 1023;

    const float* cm = g_ctxmean + b * H_;
    const float* wr = Wo + (size_t)o * H_;
    float acc = 0.f;
#pragma unroll
    for (int h = lane; h < H_; h += 32) acc += cm[h] * wr[h];
#pragma unroll
    for (int off = 16; off > 0; off >>= 1)
        acc += __shfl_xor_sync(0xFFFFFFFFu, acc, off);
    if (lane == 0) out[idx] = acc + bo[o];
}

// ---------------------------------------------------------------------------
__global__ void weights_kernel(float* __restrict__ out)
{
    int i = blockIdx.x * blockDim.x + threadIdx.x;
    if (i >= B_ * L_) return;
    int b = i >> 11;
    int k = i & (L_ - 1);
    float s = 0.f;
#pragma unroll
    for (int nh = 0; nh < NH_; nh++)
        s += g_cs[(b * NH_ + nh) * L_ + k];
    out[B_ * H_ + i] = s * (1.f / (float)(NH_ * L_));
}

// ---------------------------------------------------------------------------
extern "C" void kernel_launch(void* const* d_in, const int* in_sizes, int n_in,
                              void* d_out, int out_size)
{
    const float* x  = (const float*)d_in[0];
    const float* Wq = (const float*)d_in[1];
    const float* bq = (const float*)d_in[2];
    const float* Wk = (const float*)d_in[3];
    const float* bk = (const float*)d_in[4];
    const float* Wv = (const float*)d_in[5];
    const float* bv = (const float*)d_in[6];
    const float* Wo = (const float*)d_in[7];
    const float* bo = (const float*)d_in[8];
    float* out = (float*)d_out;

    cudaFuncSetAttribute(gemm_qk,  cudaFuncAttributeMaxDynamicSharedMemorySize, 73728);
    cudaFuncSetAttribute(rowsum_k, cudaFuncAttributeMaxDynamicSharedMemorySize, 57344);
    cudaFuncSetAttribute(colsum_k, cudaFuncAttributeMaxDynamicSharedMemorySize, 65536);

    prep_k<<<(ROWS_ * H_) / 256, 256>>>(x, Wq, Wk);

    gemm_qk<<<dim3(H_ / 128, ROWS_ / 128, 2), 256, 73728>>>(bq, bk);

    rowsum_k<<<dim3(16, HEADS_), 256, 57344>>>();
    colsum_k<<<dim3(16, HEADS_), 256, 65536>>>();

    wsum_k<<<dim3(8, B_, 8), 128>>>(x);
    ctx_k<<<HEADS_, 256>>>(Wv, bv);
    pooled_kernel<<<512, 256>>>(Wo, bo, out);
    weights_kernel<<<(B_ * L_ + 255) / 256, 256>>>(out);
}